// round 8
// baseline (speedup 1.0000x reference)
#include <cuda_runtime.h>
#include <cstdint>
#include <math.h>

#define BB 4
#define SS 2048
#define DD 1024

#define TM 128
#define TN 128
#define TK 32
#define NTHREADS 256
#define STAGES 3
#define STAGE_BYTES 32768            // A fp32 16K | B fp32 16K
#define DSM_BYTES (STAGES * STAGE_BYTES + 1024)

// ---------------------------------------------------------------------------
// Scratch (__device__ globals: allocation-guard-safe). All values stored as
// fp32 whose mantissas are pre-rounded to tf32 (RNA) by their producers.
// ---------------------------------------------------------------------------
__device__ float g_X [(size_t)BB * SS * DD];          // x (tf32)      32 MB
__device__ float g_Wt[3][(size_t)DD * DD];            // W^T (tf32)    12 MB
__device__ float g_Q [(size_t)BB * SS * DD];          // Q (tf32)      32 MB
__device__ float g_K [(size_t)BB * SS * DD];          // K (tf32)      32 MB
__device__ float g_V [(size_t)BB * SS * DD];          // V fp32        32 MB
__device__ float g_Vt[(size_t)BB * SS * DD];          // V^T (tf32)    32 MB
__device__ float g_S [(size_t)BB * SS * SS];          // scores fp32   64 MB
__device__ float g_P [(size_t)BB * SS * SS];          // probs (tf32)  64 MB

// ---------------------------------------------------------------------------
// Helpers
// ---------------------------------------------------------------------------
__device__ __forceinline__ uint32_t smem_u32(const void* p) {
    uint32_t a;
    asm("{ .reg .u64 t; cvta.to.shared.u64 t, %1; cvt.u32.u64 %0, t; }"
        : "=r"(a) : "l"(p));
    return a;
}

__device__ __forceinline__ uint32_t tf32r(float f) {
    uint32_t r;
    asm("cvt.rna.tf32.f32 %0, %1;" : "=r"(r) : "f"(f));
    return r;
}

#define LDSM4(r, a)                                                        \
    asm volatile("ldmatrix.sync.aligned.m8n8.x4.shared.b16 "               \
                 "{%0,%1,%2,%3}, [%4];"                                    \
                 : "=r"((r)[0]), "=r"((r)[1]), "=r"((r)[2]), "=r"((r)[3])  \
                 : "r"(a))

#define MMATF32(d, a, b0, b1)                                              \
    asm volatile("mma.sync.aligned.m16n8k8.row.col.f32.tf32.tf32.f32 "     \
                 "{%0,%1,%2,%3},{%4,%5,%6,%7},{%8,%9},{%0,%1,%2,%3};"      \
                 : "+f"((d)[0]), "+f"((d)[1]), "+f"((d)[2]), "+f"((d)[3])  \
                 : "r"((a)[0]), "r"((a)[1]), "r"((a)[2]), "r"((a)[3]),     \
                   "r"(b0), "r"(b1))

#define CPA16(dst, src)                                                    \
    asm volatile("cp.async.cg.shared.global [%0], [%1], 16;"               \
                 :: "r"(dst), "l"(src))
#define CPA_COMMIT()  asm volatile("cp.async.commit_group;" ::: "memory")
#define CPA_WAIT1()   asm volatile("cp.async.wait_group 1;" ::: "memory")

// ---------------------------------------------------------------------------
// Single-pass tf32 mma.sync GEMM. CTA 128x128, 3-stage cp.async, 2 CTAs/SM.
//   C[m,n] = alpha * sum_k A[m,k] * B[n,k]   (fp32/tf32, B stored K-major)
//   Warp grid 4m x 2n, warp tile 32x64.
//   TRI : skip tiles fully above the diagonal; PERQ: K limit = (by+1)*TM
//   ROUND: round output to tf32 (for Q/K, which feed later MMAs)
// SMEM tile rows are 128 B (32 fp32); SW128 swizzle (XOR bits[6:4] w/ row[2:0]).
// ---------------------------------------------------------------------------
template<bool TRI, bool PERQ, bool ROUND>
__global__ void __launch_bounds__(NTHREADS, 2)
mma_gemm(const float* __restrict__ A, int lda, long long sA,
         const float* __restrict__ B, int ldb, long long sB,
         float* __restrict__ C, int ldc, long long sC,
         int Kfull, float alpha)
{
    const int m0 = blockIdx.y * TM;
    const int n0 = blockIdx.x * TN;
    if (TRI && n0 > m0 + TM - 1) return;

    extern __shared__ char dsm[];
    const uint32_t sbase = (smem_u32(dsm) + 1023u) & ~1023u;

    const long long z = blockIdx.z;
    A += sA * z; B += sB * z;

    const int Klim = PERQ ? (int)(blockIdx.y + 1) * TM : Kfull;
    const int KB = Klim / TK;

    const int tid  = threadIdx.x;
    const int lane = tid & 31;
    const int wid  = tid >> 5;
    const int wm = (wid & 3) * 32;        // warp m offset
    const int wn = (wid >> 2) * 64;       // warp n offset

    // cp.async: rows of 128 B (8 x 16B chunks). A and B: 128 rows each,
    // 4 tasks/thread (rows arow+{0,32,64,96}).
    const int arow = tid >> 3, cu = tid & 7;
    const uint32_t aoffs =
        ((uint32_t)arow * 128u + (uint32_t)cu * 16u) ^ (((uint32_t)(arow & 7)) << 4);
    // (row+32k) & 7 == row & 7, so task i's smem offset = aoffs + i*4096.
    const float* gA = A + (long long)(m0 + arow) * lda + cu * 4;
    const float* gB = B + (long long)(n0 + arow) * ldb + cu * 4;
    const long long a32 = (long long)32 * lda;
    const long long b32 = (long long)32 * ldb;

    // ldmatrix fragment addresses (row part, swizzled; column XORed per kblk)
    const int fr = lane & 15;
    const uint32_t hb = (uint32_t)(lane >> 4) * 16u;
    uint32_t aSw[2], bSw[4];
#pragma unroll
    for (int mf = 0; mf < 2; mf++) {
        int row = wm + 16 * mf + fr;
        aSw[mf] = (uint32_t)row * 128u ^ (((uint32_t)(row & 7)) << 4);
    }
#pragma unroll
    for (int g = 0; g < 4; g++) {
        int row = wn + 16 * g + fr;
        bSw[g] = 16384u + ((uint32_t)row * 128u ^ (((uint32_t)(row & 7)) << 4));
    }

    float acc[2][8][4];
#pragma unroll
    for (int mf = 0; mf < 2; mf++)
#pragma unroll
        for (int nf = 0; nf < 8; nf++)
#pragma unroll
            for (int j = 0; j < 4; j++) acc[mf][nf][j] = 0.0f;

#define ISSUE_STAGE(sidx, k0)                                              \
    do {                                                                   \
        const uint32_t sb_ = sbase + (uint32_t)(sidx) * STAGE_BYTES;       \
        CPA16(sb_ + aoffs,          gA + (k0));                            \
        CPA16(sb_ + aoffs +  4096u, gA + (k0) + a32);                      \
        CPA16(sb_ + aoffs +  8192u, gA + (k0) + 2 * a32);                  \
        CPA16(sb_ + aoffs + 12288u, gA + (k0) + 3 * a32);                  \
        CPA16(sb_ + 16384u + aoffs,          gB + (k0));                   \
        CPA16(sb_ + 16384u + aoffs +  4096u, gB + (k0) + b32);             \
        CPA16(sb_ + 16384u + aoffs +  8192u, gB + (k0) + 2 * b32);         \
        CPA16(sb_ + 16384u + aoffs + 12288u, gB + (k0) + 3 * b32);         \
    } while (0)

    // ---- prologue: stages 0..1 ----
#pragma unroll
    for (int s = 0; s < STAGES - 1; s++) {
        if (s < KB) ISSUE_STAGE(s, s * TK);
        CPA_COMMIT();
    }

    int sidx_c = 0;
    int sidx_w = STAGES - 1;
    for (int kb = 0; kb < KB; kb++) {
        CPA_WAIT1();
        __syncthreads();

        if (kb + STAGES - 1 < KB)
            ISSUE_STAGE(sidx_w, (kb + STAGES - 1) * TK);
        CPA_COMMIT();
        if (++sidx_w == STAGES) sidx_w = 0;

        const uint32_t buf = sbase + (uint32_t)sidx_c * STAGE_BYTES;
        if (++sidx_c == STAGES) sidx_c = 0;

#pragma unroll
        for (int kblk = 0; kblk < 4; kblk++) {            // 4 x k8 per k-block
            const uint32_t kc = (uint32_t)(kblk * 32) + hb;
            uint32_t a[2][4], b[4][4];
            LDSM4(a[0], buf + (aSw[0] ^ kc));
            LDSM4(a[1], buf + (aSw[1] ^ kc));
#pragma unroll
            for (int g = 0; g < 4; g++)
                LDSM4(b[g], buf + (bSw[g] ^ kc));
            // 32 independent MMAs (all distinct accumulators)
#pragma unroll
            for (int mf = 0; mf < 2; mf++)
#pragma unroll
                for (int g = 0; g < 4; g++)
#pragma unroll
                    for (int s = 0; s < 2; s++)
                        MMATF32(acc[mf][2 * g + s], a[mf], b[g][s], b[g][s + 2]);
        }
    }
#undef ISSUE_STAGE

    // ---- epilogue ----
    const int gq = lane >> 2, t = lane & 3;
    C += sC * z;
#pragma unroll
    for (int mf = 0; mf < 2; mf++) {
#pragma unroll
        for (int nf = 0; nf < 8; nf++) {
            const int r0  = m0 + wm + 16 * mf + gq;
            const int col = n0 + wn + 8 * nf + 2 * t;
            float v0 = acc[mf][nf][0] * alpha;
            float v1 = acc[mf][nf][1] * alpha;
            float v2 = acc[mf][nf][2] * alpha;
            float v3 = acc[mf][nf][3] * alpha;
            if (ROUND) {
                v0 = __uint_as_float(tf32r(v0));
                v1 = __uint_as_float(tf32r(v1));
                v2 = __uint_as_float(tf32r(v2));
                v3 = __uint_as_float(tf32r(v3));
            }
            float2 o0, o1;
            o0.x = v0; o0.y = v1; o1.x = v2; o1.y = v3;
            *reinterpret_cast<float2*>(C + (long long)r0 * ldc + col)       = o0;
            *reinterpret_cast<float2*>(C + (long long)(r0 + 8) * ldc + col) = o1;
        }
    }
}

// ---------------------------------------------------------------------------
// fp32 -> tf32-rounded fp32 elementwise (vectorized x4)
// ---------------------------------------------------------------------------
__global__ void __launch_bounds__(256)
convert_tf32(const float* __restrict__ in, float* __restrict__ out, int n4)
{
    int i = blockIdx.x * 256 + threadIdx.x;
    if (i >= n4) return;
    float4 v = reinterpret_cast<const float4*>(in)[i];
    v.x = __uint_as_float(tf32r(v.x));
    v.y = __uint_as_float(tf32r(v.y));
    v.z = __uint_as_float(tf32r(v.z));
    v.w = __uint_as_float(tf32r(v.w));
    reinterpret_cast<float4*>(out)[i] = v;
}

// ---------------------------------------------------------------------------
// fp32 [R x C] -> transposed tf32-rounded fp32 [C x R] (per-z batch)
// ---------------------------------------------------------------------------
__global__ void __launch_bounds__(256)
transpose_tf32(const float* __restrict__ in, float* __restrict__ out,
               int R, int C, long long sIn, long long sOut)
{
    __shared__ float t[32][33];
    in  += sIn * blockIdx.z;
    out += sOut * blockIdx.z;
    const int c0 = blockIdx.x * 32, r0 = blockIdx.y * 32;
#pragma unroll
    for (int j = threadIdx.y; j < 32; j += 8)
        t[j][threadIdx.x] = in[(long long)(r0 + j) * C + c0 + threadIdx.x];
    __syncthreads();
#pragma unroll
    for (int j = threadIdx.y; j < 32; j += 8)
        out[(long long)(c0 + j) * R + r0 + threadIdx.x] =
            __uint_as_float(tf32r(t[threadIdx.x][j]));
}

// ---------------------------------------------------------------------------
// Causal row softmax: fp32 scores -> tf32-rounded probs; zero-fill to the
// 128-aligned block end so P@V needs no masking.
// ---------------------------------------------------------------------------
__global__ void __launch_bounds__(256)
softmax_causal(const float* __restrict__ S, float* __restrict__ P)
{
    const int row = blockIdx.x;          // b*S + q
    const int q   = row & (SS - 1);
    const int limit = ((q >> 7) + 1) << 7;
    const float* p = S + (long long)row * SS;
    float* po = P + (long long)row * SS;

    const int tid = threadIdx.x;
    float v[8];
    float mx = -INFINITY;
#pragma unroll
    for (int i = 0; i < 8; i++) {
        int idx = i * 256 + tid;
        v[i] = (idx <= q) ? p[idx] : -INFINITY;
        mx = fmaxf(mx, v[i]);
    }

    __shared__ float red[256];
    red[tid] = mx;
    __syncthreads();
#pragma unroll
    for (int s = 128; s > 0; s >>= 1) {
        if (tid < s) red[tid] = fmaxf(red[tid], red[tid + s]);
        __syncthreads();
    }
    mx = red[0];
    __syncthreads();

    float e[8];
    float sum = 0.0f;
#pragma unroll
    for (int i = 0; i < 8; i++) {
        e[i] = __expf(v[i] - mx);
        sum += e[i];
    }
    red[tid] = sum;
    __syncthreads();
#pragma unroll
    for (int s = 128; s > 0; s >>= 1) {
        if (tid < s) red[tid] += red[tid + s];
        __syncthreads();
    }
    const float inv = 1.0f / red[0];

#pragma unroll
    for (int i = 0; i < 8; i++) {
        int idx = i * 256 + tid;
        if (idx <= q)          po[idx] = __uint_as_float(tf32r(e[i] * inv));
        else if (idx < limit)  po[idx] = 0.0f;
    }
}

// ---------------------------------------------------------------------------
// Launch sequence (graph-capturable: kernel launches only)
// ---------------------------------------------------------------------------
extern "C" void kernel_launch(void* const* d_in, const int* in_sizes, int n_in,
                              void* d_out, int out_size)
{
    const float* x  = (const float*)d_in[0];
    const float* Wq = (const float*)d_in[1];
    const float* Wk = (const float*)d_in[2];
    const float* Wv = (const float*)d_in[3];
    float* out = (float*)d_out;

    float *X, *Wt, *Q, *K, *V, *Vt, *Sb, *P;
    cudaGetSymbolAddress((void**)&X,  g_X);
    cudaGetSymbolAddress((void**)&Wt, g_Wt);
    cudaGetSymbolAddress((void**)&Q,  g_Q);
    cudaGetSymbolAddress((void**)&K,  g_K);
    cudaGetSymbolAddress((void**)&V,  g_V);
    cudaGetSymbolAddress((void**)&Vt, g_Vt);
    cudaGetSymbolAddress((void**)&Sb, g_S);
    cudaGetSymbolAddress((void**)&P,  g_P);

    const size_t wsz = (size_t)DD * DD;
    float *Wt0 = Wt, *Wt1 = Wt + wsz, *Wt2 = Wt + 2 * wsz;

    cudaFuncSetAttribute(mma_gemm<false, false, true>,
                         cudaFuncAttributeMaxDynamicSharedMemorySize, DSM_BYTES);
    cudaFuncSetAttribute(mma_gemm<false, false, false>,
                         cudaFuncAttributeMaxDynamicSharedMemorySize, DSM_BYTES);
    cudaFuncSetAttribute(mma_gemm<true, false, false>,
                         cudaFuncAttributeMaxDynamicSharedMemorySize, DSM_BYTES);
    cudaFuncSetAttribute(mma_gemm<false, true, false>,
                         cudaFuncAttributeMaxDynamicSharedMemorySize, DSM_BYTES);

    const long long sQKV = (long long)SS * DD;
    const long long sSco = (long long)SS * SS;
    const float scale = 0.03125f;     // 1024^-0.5

    dim3 tb(32, 8);

    // 0) round x to tf32; W^T (K-major, tf32)
    const int xn4 = BB * SS * DD / 4;
    convert_tf32<<<(xn4 + 255) / 256, 256>>>(x, X, xn4);
    transpose_tf32<<<dim3(DD / 32, DD / 32, 1), tb>>>(Wq, Wt0, DD, DD, 0, 0);
    transpose_tf32<<<dim3(DD / 32, DD / 32, 1), tb>>>(Wk, Wt1, DD, DD, 0, 0);
    transpose_tf32<<<dim3(DD / 32, DD / 32, 1), tb>>>(Wv, Wt2, DD, DD, 0, 0);

    // 1) QKV projections (Q,K rounded to tf32; V plain fp32 for transpose)
    dim3 gq(DD / TN, (BB * SS) / TM, 1);
    mma_gemm<false, false, true><<<gq, NTHREADS, DSM_BYTES>>>(
        X, DD, 0, Wt0, DD, 0, Q, DD, 0, DD, 1.0f);
    mma_gemm<false, false, true><<<gq, NTHREADS, DSM_BYTES>>>(
        X, DD, 0, Wt1, DD, 0, K, DD, 0, DD, 1.0f);
    mma_gemm<false, false, false><<<gq, NTHREADS, DSM_BYTES>>>(
        X, DD, 0, Wt2, DD, 0, V, DD, 0, DD, 1.0f);

    // 2) V^T per batch (rounds to tf32): [2048,1024] -> [1024,2048]
    transpose_tf32<<<dim3(DD / 32, SS / 32, BB), tb>>>(V, Vt, SS, DD, sQKV, sQKV);

    // 3) scores = scale * Q @ K^T (tiles touching the lower triangle only)
    dim3 gs(SS / TN, SS / TM, BB);
    mma_gemm<true, false, false><<<gs, NTHREADS, DSM_BYTES>>>(
        Q, DD, sQKV, K, DD, sQKV, Sb, SS, sSco, DD, scale);

    // 4) causal softmax -> tf32 probs (+ zero-fill to 128 boundary)
    softmax_causal<<<BB * SS, 256>>>(Sb, P);

    // 5) out = P @ V  (per-q-tile K range)
    dim3 gp(DD / TN, SS / TM, BB);
    mma_gemm<false, true, false><<<gp, NTHREADS, DSM_BYTES>>>(
        P, SS, sSco, Vt, SS, sQKV, out, DD, sQKV, 0, 1.0f);
}

// round 9
// speedup vs baseline: 1.1019x; 1.1019x over previous
#include <cuda_runtime.h>
#include <cstdint>
#include <math.h>

#define BB 4
#define SS 2048
#define DD 1024

#define TM 128
#define TN 64
#define TK 32
#define NTHREADS 256
#define STAGES 3
#define STAGE_BYTES 24576            // A fp32 16K | B fp32 8K
#define DSM_BYTES (STAGES * STAGE_BYTES + 1024)

// ---------------------------------------------------------------------------
// Scratch (__device__ globals: allocation-guard-safe). All values stored as
// fp32 whose mantissas are pre-rounded to tf32 (RNA) by their producers.
// ---------------------------------------------------------------------------
__device__ float g_X [(size_t)BB * SS * DD];          // x (tf32)      32 MB
__device__ float g_Wt[3][(size_t)DD * DD];            // W^T (tf32)    12 MB
__device__ float g_Q [(size_t)BB * SS * DD];          // Q (tf32)      32 MB
__device__ float g_K [(size_t)BB * SS * DD];          // K (tf32)      32 MB
__device__ float g_V [(size_t)BB * SS * DD];          // V fp32        32 MB
__device__ float g_Vt[(size_t)BB * SS * DD];          // V^T (tf32)    32 MB
__device__ float g_S [(size_t)BB * SS * SS];          // scores fp32   64 MB
__device__ float g_P [(size_t)BB * SS * SS];          // probs (tf32)  64 MB

// ---------------------------------------------------------------------------
// Helpers
// ---------------------------------------------------------------------------
__device__ __forceinline__ uint32_t smem_u32(const void* p) {
    uint32_t a;
    asm("{ .reg .u64 t; cvta.to.shared.u64 t, %1; cvt.u32.u64 %0, t; }"
        : "=r"(a) : "l"(p));
    return a;
}

__device__ __forceinline__ uint32_t tf32r(float f) {
    uint32_t r;
    asm("cvt.rna.tf32.f32 %0, %1;" : "=r"(r) : "f"(f));
    return r;
}

#define LDSM4(r, a)                                                        \
    asm volatile("ldmatrix.sync.aligned.m8n8.x4.shared.b16 "               \
                 "{%0,%1,%2,%3}, [%4];"                                    \
                 : "=r"((r)[0]), "=r"((r)[1]), "=r"((r)[2]), "=r"((r)[3])  \
                 : "r"(a))

#define MMATF32(d, a, b0, b1)                                              \
    asm volatile("mma.sync.aligned.m16n8k8.row.col.f32.tf32.tf32.f32 "     \
                 "{%0,%1,%2,%3},{%4,%5,%6,%7},{%8,%9},{%0,%1,%2,%3};"      \
                 : "+f"((d)[0]), "+f"((d)[1]), "+f"((d)[2]), "+f"((d)[3])  \
                 : "r"((a)[0]), "r"((a)[1]), "r"((a)[2]), "r"((a)[3]),     \
                   "r"(b0), "r"(b1))

#define CPA16(dst, src)                                                    \
    asm volatile("cp.async.cg.shared.global [%0], [%1], 16;"               \
                 :: "r"(dst), "l"(src))
#define CPA_COMMIT()  asm volatile("cp.async.commit_group;" ::: "memory")
#define CPA_WAIT1()   asm volatile("cp.async.wait_group 1;" ::: "memory")

// ===========================================================================
// Shared GEMM body (CTA 128x64, 3-stage cp.async, warp tile 32x32).
// Computes acc = sum_k A[m,k] * B[n,k] over KB k-blocks of 32.
// Invoked from the two kernels below with their own prologue/epilogue.
// ===========================================================================
struct GemmCtx {
    uint32_t sbase;
    uint32_t aoffs;
    const float* gA;
    const float* gB;
    long long a32, b32;
    uint32_t aSw[2], bSw[2];
    uint32_t hb;
};

__device__ __forceinline__ void gemm_setup(GemmCtx& cx, uint32_t sbase,
                                           const float* A, int lda, int m0,
                                           const float* B, int ldb, int n0,
                                           int tid, int lane, int wid)
{
    cx.sbase = sbase;
    const int wm = (wid & 3) * 32;
    const int wn = (wid >> 2) * 32;

    const int arow = tid >> 3, cu = tid & 7;
    cx.aoffs = ((uint32_t)arow * 128u + (uint32_t)cu * 16u)
               ^ (((uint32_t)(arow & 7)) << 4);
    cx.gA = A + (long long)(m0 + arow) * lda + cu * 4;
    cx.gB = B + (long long)(n0 + arow) * ldb + cu * 4;
    cx.a32 = (long long)32 * lda;
    cx.b32 = (long long)32 * ldb;

    const int fr = lane & 15;
    cx.hb = (uint32_t)(lane >> 4) * 16u;
#pragma unroll
    for (int mf = 0; mf < 2; mf++) {
        int row = wm + 16 * mf + fr;
        cx.aSw[mf] = (uint32_t)row * 128u ^ (((uint32_t)(row & 7)) << 4);
    }
#pragma unroll
    for (int g = 0; g < 2; g++) {
        int row = wn + 16 * g + fr;
        cx.bSw[g] = 16384u + ((uint32_t)row * 128u ^ (((uint32_t)(row & 7)) << 4));
    }
}

__device__ __forceinline__ void gemm_issue(const GemmCtx& cx, int sidx, int k0)
{
    const uint32_t sb_ = cx.sbase + (uint32_t)sidx * STAGE_BYTES;
    CPA16(sb_ + cx.aoffs,          cx.gA + k0);
    CPA16(sb_ + cx.aoffs +  4096u, cx.gA + k0 + cx.a32);
    CPA16(sb_ + cx.aoffs +  8192u, cx.gA + k0 + 2 * cx.a32);
    CPA16(sb_ + cx.aoffs + 12288u, cx.gA + k0 + 3 * cx.a32);
    CPA16(sb_ + 16384u + cx.aoffs,         cx.gB + k0);
    CPA16(sb_ + 16384u + cx.aoffs + 4096u, cx.gB + k0 + cx.b32);
}

__device__ __forceinline__ void gemm_mainloop(const GemmCtx& cx, int KB,
                                              float acc[2][4][4])
{
#pragma unroll
    for (int s = 0; s < STAGES - 1; s++) {
        if (s < KB) gemm_issue(cx, s, s * TK);
        CPA_COMMIT();
    }

    int sidx_c = 0;
    int sidx_w = STAGES - 1;
    for (int kb = 0; kb < KB; kb++) {
        CPA_WAIT1();
        __syncthreads();

        if (kb + STAGES - 1 < KB)
            gemm_issue(cx, sidx_w, (kb + STAGES - 1) * TK);
        CPA_COMMIT();
        if (++sidx_w == STAGES) sidx_w = 0;

        const uint32_t buf = cx.sbase + (uint32_t)sidx_c * STAGE_BYTES;
        if (++sidx_c == STAGES) sidx_c = 0;

#pragma unroll
        for (int kblk = 0; kblk < 4; kblk++) {            // 4 x k8 per k-block
            const uint32_t kc = (uint32_t)(kblk * 32) + cx.hb;
            uint32_t a[2][4], b[2][4];
            LDSM4(a[0], buf + (cx.aSw[0] ^ kc));
            LDSM4(a[1], buf + (cx.aSw[1] ^ kc));
            LDSM4(b[0], buf + (cx.bSw[0] ^ kc));
            LDSM4(b[1], buf + (cx.bSw[1] ^ kc));
#pragma unroll
            for (int mf = 0; mf < 2; mf++)
#pragma unroll
                for (int g = 0; g < 2; g++)
#pragma unroll
                    for (int s = 0; s < 2; s++)
                        MMATF32(acc[mf][2 * g + s], a[mf], b[g][s], b[g][s + 2]);
        }
    }
}

// ---------------------------------------------------------------------------
// Generic GEMM kernel (scores / P@V).  C[m,n] = alpha * sum_k A[m,k]*B[n,k].
//   TRI : skip tiles fully above the diagonal; PERQ: K limit = (by+1)*TM.
//   Both variants reverse blockIdx.y so expensive tile-rows schedule FIRST
//   (PERQ work scales with by+1; TRI live-CTA count scales with by+1).
// ---------------------------------------------------------------------------
template<bool TRI, bool PERQ>
__global__ void __launch_bounds__(NTHREADS, 3)
mma_gemm(const float* __restrict__ A, int lda, long long sA,
         const float* __restrict__ B, int ldb, long long sB,
         float* __restrict__ C, int ldc, long long sC,
         int Kfull, float alpha)
{
    const int by = (TRI || PERQ) ? (gridDim.y - 1 - blockIdx.y) : blockIdx.y;
    const int m0 = by * TM;
    const int n0 = blockIdx.x * TN;
    if (TRI && n0 > m0 + TM - 1) return;

    extern __shared__ char dsm[];
    const uint32_t sbase = (smem_u32(dsm) + 1023u) & ~1023u;

    const long long z = blockIdx.z;
    A += sA * z; B += sB * z;

    const int Klim = PERQ ? (by + 1) * TM : Kfull;
    const int KB = Klim / TK;

    const int tid  = threadIdx.x;
    const int lane = tid & 31;
    const int wid  = tid >> 5;

    GemmCtx cx;
    gemm_setup(cx, sbase, A, lda, m0, B, ldb, n0, tid, lane, wid);

    float acc[2][4][4];
#pragma unroll
    for (int mf = 0; mf < 2; mf++)
#pragma unroll
        for (int nf = 0; nf < 4; nf++)
#pragma unroll
            for (int j = 0; j < 4; j++) acc[mf][nf][j] = 0.0f;

    gemm_mainloop(cx, KB, acc);

    // epilogue
    const int wm = (wid & 3) * 32;
    const int wn = (wid >> 2) * 32;
    const int gq = lane >> 2, t = lane & 3;
    C += sC * z;
#pragma unroll
    for (int mf = 0; mf < 2; mf++) {
#pragma unroll
        for (int nf = 0; nf < 4; nf++) {
            const int r0  = m0 + wm + 16 * mf + gq;
            const int col = n0 + wn + 8 * nf + 2 * t;
            float2 o0, o1;
            o0.x = acc[mf][nf][0] * alpha;
            o0.y = acc[mf][nf][1] * alpha;
            o1.x = acc[mf][nf][2] * alpha;
            o1.y = acc[mf][nf][3] * alpha;
            *reinterpret_cast<float2*>(C + (long long)r0 * ldc + col)       = o0;
            *reinterpret_cast<float2*>(C + (long long)(r0 + 8) * ldc + col) = o1;
        }
    }
}

// ---------------------------------------------------------------------------
// Fused QKV kernel: blockIdx.z in 0..2 selects {Wq,Wk,Wv} and {Q,K,V}.
// One launch = 3072 CTAs -> near-perfect wave packing (vs 3 x 2.3 waves).
// Q,K outputs rounded to tf32 (they feed later MMAs); V kept fp32.
// ---------------------------------------------------------------------------
__global__ void __launch_bounds__(NTHREADS, 3)
qkv_gemm(const float* __restrict__ X, const float* __restrict__ Wt,
         float* __restrict__ Qo, float* __restrict__ Ko, float* __restrict__ Vo)
{
    const int m0 = blockIdx.y * TM;
    const int n0 = blockIdx.x * TN;
    const int z  = blockIdx.z;

    extern __shared__ char dsm[];
    const uint32_t sbase = (smem_u32(dsm) + 1023u) & ~1023u;

    const float* B = Wt + (size_t)z * DD * DD;
    float* C = (z == 0) ? Qo : (z == 1) ? Ko : Vo;
    const bool roundOut = (z < 2);

    const int tid  = threadIdx.x;
    const int lane = tid & 31;
    const int wid  = tid >> 5;

    GemmCtx cx;
    gemm_setup(cx, sbase, X, DD, m0, B, DD, n0, tid, lane, wid);

    float acc[2][4][4];
#pragma unroll
    for (int mf = 0; mf < 2; mf++)
#pragma unroll
        for (int nf = 0; nf < 4; nf++)
#pragma unroll
            for (int j = 0; j < 4; j++) acc[mf][nf][j] = 0.0f;

    gemm_mainloop(cx, DD / TK, acc);

    const int wm = (wid & 3) * 32;
    const int wn = (wid >> 2) * 32;
    const int gq = lane >> 2, t = lane & 3;
#pragma unroll
    for (int mf = 0; mf < 2; mf++) {
#pragma unroll
        for (int nf = 0; nf < 4; nf++) {
            const int r0  = m0 + wm + 16 * mf + gq;
            const int col = n0 + wn + 8 * nf + 2 * t;
            float v0 = acc[mf][nf][0];
            float v1 = acc[mf][nf][1];
            float v2 = acc[mf][nf][2];
            float v3 = acc[mf][nf][3];
            if (roundOut) {
                v0 = __uint_as_float(tf32r(v0));
                v1 = __uint_as_float(tf32r(v1));
                v2 = __uint_as_float(tf32r(v2));
                v3 = __uint_as_float(tf32r(v3));
            }
            float2 o0, o1;
            o0.x = v0; o0.y = v1; o1.x = v2; o1.y = v3;
            *reinterpret_cast<float2*>(C + (long long)r0 * DD + col)       = o0;
            *reinterpret_cast<float2*>(C + (long long)(r0 + 8) * DD + col) = o1;
        }
    }
}

// ---------------------------------------------------------------------------
// fp32 -> tf32-rounded fp32 elementwise (vectorized x4)
// ---------------------------------------------------------------------------
__global__ void __launch_bounds__(256)
convert_tf32(const float* __restrict__ in, float* __restrict__ out, int n4)
{
    int i = blockIdx.x * 256 + threadIdx.x;
    if (i >= n4) return;
    float4 v = reinterpret_cast<const float4*>(in)[i];
    v.x = __uint_as_float(tf32r(v.x));
    v.y = __uint_as_float(tf32r(v.y));
    v.z = __uint_as_float(tf32r(v.z));
    v.w = __uint_as_float(tf32r(v.w));
    reinterpret_cast<float4*>(out)[i] = v;
}

// ---------------------------------------------------------------------------
// fp32 [R x C] -> transposed tf32-rounded fp32 [C x R] (per-z batch)
// ---------------------------------------------------------------------------
__global__ void __launch_bounds__(256)
transpose_tf32(const float* __restrict__ in, float* __restrict__ out,
               int R, int C, long long sIn, long long sOut)
{
    __shared__ float t[32][33];
    in  += sIn * blockIdx.z;
    out += sOut * blockIdx.z;
    const int c0 = blockIdx.x * 32, r0 = blockIdx.y * 32;
#pragma unroll
    for (int j = threadIdx.y; j < 32; j += 8)
        t[j][threadIdx.x] = in[(long long)(r0 + j) * C + c0 + threadIdx.x];
    __syncthreads();
#pragma unroll
    for (int j = threadIdx.y; j < 32; j += 8)
        out[(long long)(c0 + j) * R + r0 + threadIdx.x] =
            __uint_as_float(tf32r(t[threadIdx.x][j]));
}

// ---------------------------------------------------------------------------
// Causal row softmax: fp32 scores -> tf32-rounded probs; zero-fill to the
// 128-aligned block end so P@V needs no masking.
// ---------------------------------------------------------------------------
__global__ void __launch_bounds__(256)
softmax_causal(const float* __restrict__ S, float* __restrict__ P)
{
    const int row = blockIdx.x;          // b*S + q
    const int q   = row & (SS - 1);
    const int limit = ((q >> 7) + 1) << 7;
    const float* p = S + (long long)row * SS;
    float* po = P + (long long)row * SS;

    const int tid = threadIdx.x;
    float v[8];
    float mx = -INFINITY;
#pragma unroll
    for (int i = 0; i < 8; i++) {
        int idx = i * 256 + tid;
        v[i] = (idx <= q) ? p[idx] : -INFINITY;
        mx = fmaxf(mx, v[i]);
    }

    __shared__ float red[256];
    red[tid] = mx;
    __syncthreads();
#pragma unroll
    for (int s = 128; s > 0; s >>= 1) {
        if (tid < s) red[tid] = fmaxf(red[tid], red[tid + s]);
        __syncthreads();
    }
    mx = red[0];
    __syncthreads();

    float e[8];
    float sum = 0.0f;
#pragma unroll
    for (int i = 0; i < 8; i++) {
        e[i] = __expf(v[i] - mx);
        sum += e[i];
    }
    red[tid] = sum;
    __syncthreads();
#pragma unroll
    for (int s = 128; s > 0; s >>= 1) {
        if (tid < s) red[tid] += red[tid + s];
        __syncthreads();
    }
    const float inv = 1.0f / red[0];

#pragma unroll
    for (int i = 0; i < 8; i++) {
        int idx = i * 256 + tid;
        if (idx <= q)          po[idx] = __uint_as_float(tf32r(e[i] * inv));
        else if (idx < limit)  po[idx] = 0.0f;
    }
}

// ---------------------------------------------------------------------------
// Launch sequence (graph-capturable: kernel launches only)
// ---------------------------------------------------------------------------
extern "C" void kernel_launch(void* const* d_in, const int* in_sizes, int n_in,
                              void* d_out, int out_size)
{
    const float* x  = (const float*)d_in[0];
    const float* Wq = (const float*)d_in[1];
    const float* Wk = (const float*)d_in[2];
    const float* Wv = (const float*)d_in[3];
    float* out = (float*)d_out;

    float *X, *Wt, *Q, *K, *V, *Vt, *Sb, *P;
    cudaGetSymbolAddress((void**)&X,  g_X);
    cudaGetSymbolAddress((void**)&Wt, g_Wt);
    cudaGetSymbolAddress((void**)&Q,  g_Q);
    cudaGetSymbolAddress((void**)&K,  g_K);
    cudaGetSymbolAddress((void**)&V,  g_V);
    cudaGetSymbolAddress((void**)&Vt, g_Vt);
    cudaGetSymbolAddress((void**)&Sb, g_S);
    cudaGetSymbolAddress((void**)&P,  g_P);

    const size_t wsz = (size_t)DD * DD;
    float *Wt0 = Wt, *Wt1 = Wt + wsz, *Wt2 = Wt + 2 * wsz;

    cudaFuncSetAttribute(qkv_gemm,
                         cudaFuncAttributeMaxDynamicSharedMemorySize, DSM_BYTES);
    cudaFuncSetAttribute(mma_gemm<true, false>,
                         cudaFuncAttributeMaxDynamicSharedMemorySize, DSM_BYTES);
    cudaFuncSetAttribute(mma_gemm<false, true>,
                         cudaFuncAttributeMaxDynamicSharedMemorySize, DSM_BYTES);

    const long long sQKV = (long long)SS * DD;
    const long long sSco = (long long)SS * SS;
    const float scale = 0.03125f;     // 1024^-0.5

    dim3 tb(32, 8);

    // 0) round x to tf32; W^T (K-major, tf32)
    const int xn4 = BB * SS * DD / 4;
    convert_tf32<<<(xn4 + 255) / 256, 256>>>(x, X, xn4);
    transpose_tf32<<<dim3(DD / 32, DD / 32, 1), tb>>>(Wq, Wt0, DD, DD, 0, 0);
    transpose_tf32<<<dim3(DD / 32, DD / 32, 1), tb>>>(Wk, Wt1, DD, DD, 0, 0);
    transpose_tf32<<<dim3(DD / 32, DD / 32, 1), tb>>>(Wv, Wt2, DD, DD, 0, 0);

    // 1) Fused QKV projection: one launch, z selects W / output
    dim3 gq(DD / TN, (BB * SS) / TM, 3);
    qkv_gemm<<<gq, NTHREADS, DSM_BYTES>>>(X, Wt, Q, K, V);

    // 2) V^T per batch (rounds to tf32): [2048,1024] -> [1024,2048]
    transpose_tf32<<<dim3(DD / 32, SS / 32, BB), tb>>>(V, Vt, SS, DD, sQKV, sQKV);

    // 3) scores = scale * Q @ K^T (lower-triangle tiles; heavy rows first)
    dim3 gs(SS / TN, SS / TM, BB);
    mma_gemm<true, false><<<gs, NTHREADS, DSM_BYTES>>>(
        Q, DD, sQKV, K, DD, sQKV, Sb, SS, sSco, DD, scale);

    // 4) causal softmax -> tf32 probs (+ zero-fill to 128 boundary)
    softmax_causal<<<BB * SS, 256>>>(Sb, P);

    // 5) out = P @ V  (per-q-tile K range; heavy rows first)
    dim3 gp(DD / TN, SS / TM, BB);
    mma_gemm<false, true><<<gp, NTHREADS, DSM_BYTES>>>(
        P, SS, sSco, Vt, SS, sQKV, out, DD, sQKV, 0, 1.0f);
}